// round 17
// baseline (speedup 1.0000x reference)
#include <cuda_runtime.h>
#include <cuda_fp16.h>
#include <cuda_fp8.h>
#include <math.h>

#define NN 1500000
#define EE 12000000
#define CH 4096     // staged 8B edge records per chunk (32KB smem)

// ---- device scratch (no allocation allowed) ----
__device__ uint4   g_hxA[NN];          // 24 MB : 9 x e4m3 node feats, padded 16B
__device__ uint4   g_hxB[NN];          // 24 MB
__device__ int     g_rowptr[NN + 1];
__device__ int     g_cursor[NN];
__device__ int     g_bsums[1024];
__device__ uint2   g_perm[(size_t)EE]; // 96 MB {src, half2(ax,ay)} by dst

// Pack 9 floats -> fp8 e4m3 record (16B), ONE STG.128.
__device__ __forceinline__ void store_f8(uint4* base, size_t i, const float* h) {
    unsigned int p01 = __nv_cvt_float2_to_fp8x2(make_float2(h[0], h[1]), __NV_SATFINITE, __NV_E4M3);
    unsigned int p23 = __nv_cvt_float2_to_fp8x2(make_float2(h[2], h[3]), __NV_SATFINITE, __NV_E4M3);
    unsigned int p45 = __nv_cvt_float2_to_fp8x2(make_float2(h[4], h[5]), __NV_SATFINITE, __NV_E4M3);
    unsigned int p67 = __nv_cvt_float2_to_fp8x2(make_float2(h[6], h[7]), __NV_SATFINITE, __NV_E4M3);
    unsigned int p8  = __nv_cvt_float_to_fp8(h[8], __NV_SATFINITE, __NV_E4M3);
    uint4 q;
    q.x = (p01 & 0xFFFFu) | (p23 << 16);
    q.y = (p45 & 0xFFFFu) | (p67 << 16);
    q.z = p8 & 0xFFu;
    q.w = 0u;
    base[i] = q;
}

// Gather 9 fp8 node features -> floats. ONE LDG.128.
__device__ __forceinline__ void load_f8(const uint4* base, size_t i, float* f) {
    uint4 q = __ldg(base + i);
    __half2_raw r01 = __nv_cvt_fp8x2_to_halfraw2((__nv_fp8x2_storage_t)(q.x & 0xFFFFu), __NV_E4M3);
    __half2_raw r23 = __nv_cvt_fp8x2_to_halfraw2((__nv_fp8x2_storage_t)(q.x >> 16), __NV_E4M3);
    __half2_raw r45 = __nv_cvt_fp8x2_to_halfraw2((__nv_fp8x2_storage_t)(q.y & 0xFFFFu), __NV_E4M3);
    __half2_raw r67 = __nv_cvt_fp8x2_to_halfraw2((__nv_fp8x2_storage_t)(q.y >> 16), __NV_E4M3);
    __half_raw  r8  = __nv_cvt_fp8_to_halfraw((__nv_fp8_storage_t)(q.z & 0xFFu), __NV_E4M3);
    float2 a = __half22float2(*(__half2*)&r01);
    float2 b = __half22float2(*(__half2*)&r23);
    float2 c = __half22float2(*(__half2*)&r45);
    float2 d = __half22float2(*(__half2*)&r67);
    f[0] = a.x; f[1] = a.y; f[2] = b.x; f[3] = b.y;
    f[4] = c.x; f[5] = c.y; f[6] = d.x; f[7] = d.y;
    f[8] = __half2float(*(__half*)&r8);
}

// ---------------------------------------------------------------------------
__global__ void k_zero(int n) {
    int i = blockIdx.x * blockDim.x + threadIdx.x;
    if (i < n) g_cursor[i] = 0;
}

// ---------------------------------------------------------------------------
__global__ void k_hist(const int* __restrict__ ei, int E) {
    int t = blockIdx.x * blockDim.x + threadIdx.x;
    int e0 = t * 4;
    if (e0 >= E) return;
    int4 d4 = *(const int4*)(ei + E + e0);
    atomicAdd(&g_cursor[d4.x], 1);
    atomicAdd(&g_cursor[d4.y], 1);
    atomicAdd(&g_cursor[d4.z], 1);
    atomicAdd(&g_cursor[d4.w], 1);
}

// ---------------------------------------------------------------------------
__global__ void k_scan1(int n) {   // 4096 elems / block
    __shared__ int s[256];
    int tid = threadIdx.x;
    int base = blockIdx.x * 4096 + tid * 16;
    int v[16];
    int sum = 0;
#pragma unroll
    for (int j = 0; j < 16; j++) {
        int idx = base + j;
        v[j] = (idx < n) ? g_cursor[idx] : 0;
        sum += v[j];
    }
    s[tid] = sum;
    __syncthreads();
    for (int off = 1; off < 256; off <<= 1) {
        int t = (tid >= off) ? s[tid - off] : 0;
        __syncthreads();
        s[tid] += t;
        __syncthreads();
    }
    int excl = s[tid] - sum;
    if (tid == 255) g_bsums[blockIdx.x] = s[255];
    int run = excl;
#pragma unroll
    for (int j = 0; j < 16; j++) {
        int idx = base + j;
        if (idx < n) g_rowptr[idx] = run;
        run += v[j];
    }
}

__global__ void k_scan2(int nb) {
    __shared__ int s[512];
    int tid = threadIdx.x;
    int val = (tid < nb) ? g_bsums[tid] : 0;
    s[tid] = val;
    __syncthreads();
    for (int off = 1; off < 512; off <<= 1) {
        int t = (tid >= off) ? s[tid - off] : 0;
        __syncthreads();
        s[tid] += t;
        __syncthreads();
    }
    if (tid < nb) g_bsums[tid] = s[tid] - val;
}

__global__ void k_scan3(int n, int E) {
    int i = blockIdx.x * blockDim.x + threadIdx.x;
    if (i >= n) return;
    int r = g_rowptr[i] + g_bsums[i >> 12];
    g_rowptr[i] = r;
    g_cursor[i] = r;
    if (i == 0) g_rowptr[n] = E;
}

// ---------------------------------------------------------------------------
__global__ void k_scatter(const int* __restrict__ ei,
                          const float* __restrict__ attr, int E) {
    int t = blockIdx.x * blockDim.x + threadIdx.x;
    int e0 = t * 4;
    if (e0 >= E) return;
    int4 s4 = *(const int4*)(ei + e0);
    int4 d4 = *(const int4*)(ei + E + e0);
    float4 a0 = *(const float4*)(attr + (size_t)e0 * 2);
    float4 a1 = *(const float4*)(attr + (size_t)e0 * 2 + 4);
    int src[4] = {s4.x, s4.y, s4.z, s4.w};
    int dst[4] = {d4.x, d4.y, d4.z, d4.w};
    __half2 at[4] = {__floats2half2_rn(a0.x, a0.y), __floats2half2_rn(a0.z, a0.w),
                     __floats2half2_rn(a1.x, a1.y), __floats2half2_rn(a1.z, a1.w)};
#pragma unroll
    for (int k = 0; k < 4; k++) {
        int pos = atomicAdd(&g_cursor[dst[k]], 1);
        uint2 rec;
        rec.x = (unsigned int)src[k];
        rec.y = *(unsigned int*)&at[k];
        g_perm[pos] = rec;
    }
}

// ---------------------------------------------------------------------------
// Conv1 fused with input transform: gathers x[src] (4B, L2-resident) and
// computes h_src = Wx1*x+bx1 on the fly. Writes fp8 hxA.
// ---------------------------------------------------------------------------
__global__ void k_conv1(const float* __restrict__ x,
                        const float* __restrict__ Wx1, const float* __restrict__ bx1,
                        const float* __restrict__ We, const float* __restrict__ be,
                        const float* __restrict__ Wo, const float* __restrict__ bo,
                        const float* __restrict__ Wxn, const float* __restrict__ bxn,
                        int n) {
    __shared__ uint2 sbuf[CH];
    __shared__ float sW1[9], sB1[9], sWe[18], sbe[9], sWo[81], sbo[9], sWx[81], sbx[9];
    for (int j = threadIdx.x; j < 9;  j += blockDim.x) { sW1[j] = Wx1[j]; sB1[j] = bx1[j]; }
    for (int j = threadIdx.x; j < 18; j += blockDim.x) sWe[j] = We[j];
    for (int j = threadIdx.x; j < 9;  j += blockDim.x) sbe[j] = be[j];
    for (int j = threadIdx.x; j < 81; j += blockDim.x) sWo[j] = Wo[j];
    for (int j = threadIdx.x; j < 9;  j += blockDim.x) sbo[j] = bo[j];
    for (int j = threadIdx.x; j < 81; j += blockDim.x) sWx[j] = Wxn[j];
    for (int j = threadIdx.x; j < 9;  j += blockDim.x) sbx[j] = bxn[j];

    int b0 = blockIdx.x * blockDim.x;
    int i  = b0 + threadIdx.x;
    int beg = 0, end = 0;
    if (i < n) { beg = __ldg(&g_rowptr[i]); end = __ldg(&g_rowptr[i + 1]); }
    int lastNode = min(b0 + (int)blockDim.x, n);
    int beg_blk = __ldg(&g_rowptr[b0]);
    int end_blk = __ldg(&g_rowptr[lastNode]);

    float acc[9] = {0, 0, 0, 0, 0, 0, 0, 0, 0};

    for (int c0 = beg_blk; c0 < end_blk; c0 += CH) {
        int cnt = min(CH, end_blk - c0);
        __syncthreads();
        for (int j = threadIdx.x; j < cnt; j += blockDim.x)
            sbuf[j] = __ldcs(&g_perm[c0 + j]);
        __syncthreads();

        int lo = max(beg, c0) - c0;
        int hi = min(end, c0 + cnt) - c0;
        int e = lo;
        for (; e + 4 <= hi; e += 4) {
            uint2 r[4];
            float xv[4];
#pragma unroll
            for (int k = 0; k < 4; k++) r[k] = sbuf[e + k];
#pragma unroll
            for (int k = 0; k < 4; k++) xv[k] = __ldg(x + r[k].x);
#pragma unroll
            for (int k = 0; k < 4; k++) {
                float2 a = __half22float2(*(const __half2*)&r[k].y);
#pragma unroll
                for (int j = 0; j < 9; j++) {
                    float hj = fmaf(sW1[j], xv[k], sB1[j]);
                    float ew = fmaf(sWe[2 * j], a.x, fmaf(sWe[2 * j + 1], a.y, sbe[j]));
                    acc[j] = fmaf(hj, ew, acc[j]);
                }
            }
        }
        for (; e < hi; e++) {
            uint2 r0 = sbuf[e];
            float xv = __ldg(x + r0.x);
            float2 a = __half22float2(*(const __half2*)&r0.y);
#pragma unroll
            for (int j = 0; j < 9; j++) {
                float hj = fmaf(sW1[j], xv, sB1[j]);
                float ew = fmaf(sWe[2 * j], a.x, fmaf(sWe[2 * j + 1], a.y, sbe[j]));
                acc[j] = fmaf(hj, ew, acc[j]);
            }
        }
    }

    if (i >= n) return;

    float r[9];
#pragma unroll
    for (int o = 0; o < 9; o++) {
        float s = sbo[o];
#pragma unroll
        for (int j = 0; j < 9; j++) s = fmaf(sWo[o * 9 + j], acc[j], s);
        r[o] = fmaxf(s, 0.f);
    }
    float h[9];
#pragma unroll
    for (int o = 0; o < 9; o++) {
        float s = sbx[o];
#pragma unroll
        for (int j = 0; j < 9; j++) s = fmaf(sWx[o * 9 + j], r[j], s);
        h[o] = s;
    }
    store_f8(g_hxA, (size_t)i, h);
}

// ---------------------------------------------------------------------------
// Conv2: hxA -> hxB (fp8 gathers, identical mainloop to R16 conv<9>)
// ---------------------------------------------------------------------------
__global__ void k_conv2(const float* __restrict__ We, const float* __restrict__ be,
                        const float* __restrict__ Wo, const float* __restrict__ bo,
                        const float* __restrict__ Wxn, const float* __restrict__ bxn,
                        int n) {
    __shared__ uint2 sbuf[CH];
    __shared__ float sWe[18], sbe[9], sWo[81], sbo[9], sWx[81], sbx[9];
    for (int j = threadIdx.x; j < 18; j += blockDim.x) sWe[j] = We[j];
    for (int j = threadIdx.x; j < 9;  j += blockDim.x) sbe[j] = be[j];
    for (int j = threadIdx.x; j < 81; j += blockDim.x) sWo[j] = Wo[j];
    for (int j = threadIdx.x; j < 9;  j += blockDim.x) sbo[j] = bo[j];
    for (int j = threadIdx.x; j < 81; j += blockDim.x) sWx[j] = Wxn[j];
    for (int j = threadIdx.x; j < 9;  j += blockDim.x) sbx[j] = bxn[j];

    int b0 = blockIdx.x * blockDim.x;
    int i  = b0 + threadIdx.x;
    int beg = 0, end = 0;
    if (i < n) { beg = __ldg(&g_rowptr[i]); end = __ldg(&g_rowptr[i + 1]); }
    int lastNode = min(b0 + (int)blockDim.x, n);
    int beg_blk = __ldg(&g_rowptr[b0]);
    int end_blk = __ldg(&g_rowptr[lastNode]);

    float acc[9] = {0, 0, 0, 0, 0, 0, 0, 0, 0};

    for (int c0 = beg_blk; c0 < end_blk; c0 += CH) {
        int cnt = min(CH, end_blk - c0);
        __syncthreads();
        for (int j = threadIdx.x; j < cnt; j += blockDim.x)
            sbuf[j] = __ldcs(&g_perm[c0 + j]);
        __syncthreads();

        int lo = max(beg, c0) - c0;
        int hi = min(end, c0 + cnt) - c0;
        int e = lo;
        for (; e + 4 <= hi; e += 4) {
            uint2 r[4];
            float F[4][9];
#pragma unroll
            for (int k = 0; k < 4; k++) r[k] = sbuf[e + k];
#pragma unroll
            for (int k = 0; k < 4; k++) load_f8(g_hxA, (size_t)r[k].x, F[k]);
#pragma unroll
            for (int k = 0; k < 4; k++) {
                float2 a = __half22float2(*(const __half2*)&r[k].y);
#pragma unroll
                for (int j = 0; j < 9; j++) {
                    float ew = fmaf(sWe[2 * j], a.x, fmaf(sWe[2 * j + 1], a.y, sbe[j]));
                    acc[j] = fmaf(F[k][j], ew, acc[j]);
                }
            }
        }
        for (; e < hi; e++) {
            uint2 r0 = sbuf[e];
            float A[9];
            load_f8(g_hxA, (size_t)r0.x, A);
            float2 a = __half22float2(*(const __half2*)&r0.y);
#pragma unroll
            for (int j = 0; j < 9; j++) {
                float ew = fmaf(sWe[2 * j], a.x, fmaf(sWe[2 * j + 1], a.y, sbe[j]));
                acc[j] = fmaf(A[j], ew, acc[j]);
            }
        }
    }

    if (i >= n) return;

    float r[9];
#pragma unroll
    for (int o = 0; o < 9; o++) {
        float s = sbo[o];
#pragma unroll
        for (int j = 0; j < 9; j++) s = fmaf(sWo[o * 9 + j], acc[j], s);
        r[o] = fmaxf(s, 0.f);
    }
    float h[9];
#pragma unroll
    for (int o = 0; o < 9; o++) {
        float s = sbx[o];
#pragma unroll
        for (int j = 0; j < 9; j++) s = fmaf(sWx[o * 9 + j], r[j], s);
        h[o] = s;
    }
    store_f8(g_hxB, (size_t)i, h);
}

// ---------------------------------------------------------------------------
// Fused conv3 + head: thread per tracklet walks its 6 consecutive node
// segments (reading hxB), builds v[24] in registers, then MLP + log_softmax.
// ---------------------------------------------------------------------------
__global__ void k_conv3_head(const float* __restrict__ We, const float* __restrict__ be,
                             const float* __restrict__ Wo3, const float* __restrict__ bo3,
                             const float* __restrict__ W1, const float* __restrict__ b1,
                             const float* __restrict__ W2, const float* __restrict__ b2,
                             float* __restrict__ out, int T) {
    __shared__ uint2 sbuf[CH];
    __shared__ float sWe[18], sbe[9], sWo3[36], sbo3[4], sW1[192], sb1[8], sW2[32], sb2[4];
    for (int j = threadIdx.x; j < 18;  j += blockDim.x) sWe[j]  = We[j];
    for (int j = threadIdx.x; j < 9;   j += blockDim.x) sbe[j]  = be[j];
    for (int j = threadIdx.x; j < 36;  j += blockDim.x) sWo3[j] = Wo3[j];
    for (int j = threadIdx.x; j < 4;   j += blockDim.x) sbo3[j] = bo3[j];
    for (int j = threadIdx.x; j < 192; j += blockDim.x) sW1[j]  = W1[j];
    for (int j = threadIdx.x; j < 8;   j += blockDim.x) sb1[j]  = b1[j];
    for (int j = threadIdx.x; j < 32;  j += blockDim.x) sW2[j]  = W2[j];
    for (int j = threadIdx.x; j < 4;   j += blockDim.x) sb2[j]  = b2[j];

    int b0 = blockIdx.x * blockDim.x;   // tracklet base
    int t  = b0 + threadIdx.x;
    int lastT = min(b0 + (int)blockDim.x, T);
    int beg_blk = __ldg(&g_rowptr[b0 * 6]);
    int end_blk = __ldg(&g_rowptr[lastT * 6]);

    int nbeg[7];
    if (t < T) {
#pragma unroll
        for (int k = 0; k < 7; k++) nbeg[k] = __ldg(&g_rowptr[t * 6 + k]);
    } else {
#pragma unroll
        for (int k = 0; k < 7; k++) nbeg[k] = end_blk;  // empty segments
    }

    float v[24];
    float acc[9] = {0, 0, 0, 0, 0, 0, 0, 0, 0};
    int curNode = 0;

    for (int c0 = beg_blk; c0 < end_blk; c0 += CH) {
        int cnt = min(CH, end_blk - c0);
        __syncthreads();
        for (int j = threadIdx.x; j < cnt; j += blockDim.x)
            sbuf[j] = __ldcs(&g_perm[c0 + j]);
        __syncthreads();

        while (curNode < 6) {
            int lo = max(nbeg[curNode], c0) - c0;
            int hi = min(nbeg[curNode + 1], c0 + cnt) - c0;
            int e = lo;
            for (; e + 4 <= hi; e += 4) {
                uint2 r[4];
                float F[4][9];
#pragma unroll
                for (int k = 0; k < 4; k++) r[k] = sbuf[e + k];
#pragma unroll
                for (int k = 0; k < 4; k++) load_f8(g_hxB, (size_t)r[k].x, F[k]);
#pragma unroll
                for (int k = 0; k < 4; k++) {
                    float2 a = __half22float2(*(const __half2*)&r[k].y);
#pragma unroll
                    for (int j = 0; j < 9; j++) {
                        float ew = fmaf(sWe[2 * j], a.x, fmaf(sWe[2 * j + 1], a.y, sbe[j]));
                        acc[j] = fmaf(F[k][j], ew, acc[j]);
                    }
                }
            }
            for (; e < hi; e++) {
                uint2 r0 = sbuf[e];
                float A[9];
                load_f8(g_hxB, (size_t)r0.x, A);
                float2 a = __half22float2(*(const __half2*)&r0.y);
#pragma unroll
                for (int j = 0; j < 9; j++) {
                    float ew = fmaf(sWe[2 * j], a.x, fmaf(sWe[2 * j + 1], a.y, sbe[j]));
                    acc[j] = fmaf(A[j], ew, acc[j]);
                }
            }
            if (nbeg[curNode + 1] <= c0 + cnt) {
                // node segment complete -> finalize conv3 output for this node
#pragma unroll
                for (int o = 0; o < 4; o++) {
                    float s = sbo3[o];
#pragma unroll
                    for (int j = 0; j < 9; j++) s = fmaf(sWo3[o * 9 + j], acc[j], s);
                    v[curNode * 4 + o] = fmaxf(s, 0.f);
                }
#pragma unroll
                for (int j = 0; j < 9; j++) acc[j] = 0.f;
                curNode++;
            } else {
                break;  // segment continues in next chunk
            }
        }
    }

    if (t >= T) return;

    float y1[8];
#pragma unroll
    for (int o = 0; o < 8; o++) {
        float s = sb1[o];
#pragma unroll
        for (int j = 0; j < 24; j++) s = fmaf(sW1[o * 24 + j], v[j], s);
        y1[o] = fmaxf(s, 0.f);
    }
    float y2[4];
#pragma unroll
    for (int o = 0; o < 4; o++) {
        float s = sb2[o];
#pragma unroll
        for (int j = 0; j < 8; j++) s = fmaf(sW2[o * 8 + j], y1[j], s);
        y2[o] = s;
    }
    float mx = fmaxf(fmaxf(y2[0], y2[1]), fmaxf(y2[2], y2[3]));
    float se = expf(y2[0] - mx) + expf(y2[1] - mx) + expf(y2[2] - mx) + expf(y2[3] - mx);
    float lse = mx + logf(se);
    *(float4*)(out + (size_t)t * 4) =
        make_float4(y2[0] - lse, y2[1] - lse, y2[2] - lse, y2[3] - lse);
}

// ---------------------------------------------------------------------------
extern "C" void kernel_launch(void* const* d_in, const int* in_sizes, int n_in,
                              void* d_out, int out_size) {
    const float* x    = (const float*)d_in[0];
    const int*   ei   = (const int*)  d_in[1];
    const float* attr = (const float*)d_in[2];
    const float* Wx1  = (const float*)d_in[3];
    const float* bx1  = (const float*)d_in[4];
    const float* We1  = (const float*)d_in[5];
    const float* be1  = (const float*)d_in[6];
    const float* Wo1  = (const float*)d_in[7];
    const float* bo1  = (const float*)d_in[8];
    const float* Wx2  = (const float*)d_in[9];
    const float* bx2  = (const float*)d_in[10];
    const float* We2  = (const float*)d_in[11];
    const float* be2  = (const float*)d_in[12];
    const float* Wo2  = (const float*)d_in[13];
    const float* bo2  = (const float*)d_in[14];
    const float* Wx3  = (const float*)d_in[15];
    const float* bx3  = (const float*)d_in[16];
    const float* We3  = (const float*)d_in[17];
    const float* be3  = (const float*)d_in[18];
    const float* Wo3  = (const float*)d_in[19];
    const float* bo3  = (const float*)d_in[20];
    const float* W1   = (const float*)d_in[21];
    const float* b1   = (const float*)d_in[22];
    const float* W2   = (const float*)d_in[23];
    const float* b2   = (const float*)d_in[24];

    const int N = in_sizes[0];       // 1,500,000
    const int E = in_sizes[2] / 2;   // 12,000,000
    const int T = N / 6;

    const int TB = 256;
    int nodeBlocks = (N + TB - 1) / TB;
    int edgeBlocks = (E / 4 + TB - 1) / TB;
    int scanBlocks = (N + 4095) / 4096;

    k_zero<<<nodeBlocks, TB>>>(N);
    k_hist<<<edgeBlocks, TB>>>(ei, E);
    k_scan1<<<scanBlocks, TB>>>(N);
    k_scan2<<<1, 512>>>(scanBlocks);
    k_scan3<<<nodeBlocks, TB>>>(N, E);
    k_scatter<<<edgeBlocks, TB>>>(ei, attr, E);

    k_conv1<<<nodeBlocks, TB>>>(x, Wx1, bx1, We1, be1, Wo1, bo1, Wx2, bx2, N);
    k_conv2<<<nodeBlocks, TB>>>(We2, be2, Wo2, bo2, Wx3, bx3, N);
    k_conv3_head<<<(T + TB - 1) / TB, TB>>>(We3, be3, Wo3, bo3, W1, b1, W2, b2,
                                            (float*)d_out, T);
}